// round 5
// baseline (speedup 1.0000x reference)
#include <cuda_runtime.h>
#include <math.h>

#define B_   256
#define T_   256
#define D_   512
#define H_   512
#define O_   256
#define EPS_ 1e-5f

#define G_   128       // persistent CTAs = 64 col-groups x 2 batch-halves
#define CG_  64        // column groups
#define HC_  8         // feature columns per col-group
#define NQ_  32        // batch quads per half (128 batch elems)
#define NKG_ 16        // k-groups
#define KG_  32        // k per group
#define NT_  512       // 32 quads x 16 k-groups
#define NW_  (NT_/32)
#define NS_  (T_ + 2)  // wavefront steps

typedef unsigned long long ull;

// ---------------- static device scratch ----------------
__device__ float d_xT[(size_t)T_ * D_ * B_];   // [t][k][i]
__device__ float d_h0 [2][H_ * B_];            // ping-pong  [k][i]
__device__ float d_hm0[2][H_ * B_];            // ping-pong
__device__ float d_hm1[H_ * B_];               // single buffer
__device__ float d_part[2][3 * CG_ * 2 * 16];  // BN partial stats
__device__ unsigned d_pcnt[CG_];               // partner-pair barrier counters

__device__ unsigned          g_cnt;
__device__ volatile unsigned g_gen;

// ---------------- packed f32x2 helpers ----------------
__device__ __forceinline__ ull pk2(float x, float y) {
    ull r; asm("mov.b64 %0, {%1, %2};" : "=l"(r) : "f"(x), "f"(y)); return r;
}
__device__ __forceinline__ void upk2(float& x, float& y, ull v) {
    asm("mov.b64 {%0, %1}, %2;" : "=f"(x), "=f"(y) : "l"(v));
}
__device__ __forceinline__ void fma2(ull& d, ull a, ull b) {
    asm("fma.rn.f32x2 %0, %1, %2, %0;" : "+l"(d) : "l"(a), "l"(b));
}

// ---------------- software grid barrier ----------------
__device__ __forceinline__ void gsync() {
    __syncthreads();
    if (threadIdx.x == 0) {
        __threadfence();
        unsigned my = g_gen;
        if (atomicAdd(&g_cnt, 1u) == (unsigned)(G_ - 1)) {
            g_cnt = 0u;
            __threadfence();
            g_gen = my + 1u;
        } else {
            while (g_gen == my) { __nanosleep(32); }
            __threadfence();
        }
    }
    __syncthreads();
}

// ---------------- partner stats exchange ----------------
// sfull[48] already holds this CTA-half's full sums per (cell, 2c+stat).
// Produces global sums in scomb[48].
__device__ __forceinline__ void stats_exchange(int phase, unsigned tgt,
                                               int cg, int b,
                                               const float* sfull, float* scomb) {
    const int tid = threadIdx.x;
    __syncthreads();
    if (tid < 48) {
        int cell = tid >> 4, q = tid & 15;
        float f = sfull[tid];
        scomb[tid] = f;
        __stcg(&d_part[phase][((cell * CG_ + cg) * 2 + b) * 16 + q], f);
        __threadfence();
    }
    __syncthreads();
    if (tid == 0) {
        atomicAdd(&d_pcnt[cg], 1u);
        while (__ldcg(&d_pcnt[cg]) < tgt) { __nanosleep(32); }
    }
    __syncthreads();
    if (tid < 48) {
        int cell = tid >> 4, q = tid & 15;
        scomb[tid] += __ldcg(&d_part[phase][((cell * CG_ + cg) * 2 + (1 - b)) * 16 + q]);
    }
    __syncthreads();
}

// ---------------- block allreduce (head) ----------------
__device__ __forceinline__ float block_allreduce_max(float v, float* s) {
    __syncthreads();
    #pragma unroll
    for (int off = 16; off > 0; off >>= 1)
        v = fmaxf(v, __shfl_xor_sync(0xffffffffu, v, off));
    if ((threadIdx.x & 31) == 0) s[threadIdx.x >> 5] = v;
    __syncthreads();
    float m = s[0];
    #pragma unroll
    for (int w = 1; w < NW_; w++) m = fmaxf(m, s[w]);
    return m;
}
__device__ __forceinline__ float block_allreduce_sum(float v, float* s) {
    __syncthreads();
    #pragma unroll
    for (int off = 16; off > 0; off >>= 1)
        v += __shfl_xor_sync(0xffffffffu, v, off);
    if ((threadIdx.x & 31) == 0) s[threadIdx.x >> 5] = v;
    __syncthreads();
    float r = 0.f;
    #pragma unroll
    for (int w = 0; w < NW_; w++) r += s[w];
    return r;
}

// ---------------- transpose x: [B][T][D] -> [T][D][B] ----------------
__global__ void transpose_kernel(const float* __restrict__ x) {
    __shared__ float sm[32][33];
    int t  = blockIdx.x;
    int k0 = blockIdx.y * 32;
    int i0 = blockIdx.z * 32;
    int tx = threadIdx.x, ty = threadIdx.y;
    sm[ty][tx] = x[((size_t)(i0 + ty) * T_ + t) * D_ + (k0 + tx)];
    __syncthreads();
    d_xT[((size_t)t * D_ + (k0 + ty)) * B_ + (i0 + tx)] = sm[tx][ty];
}

// dynamic smem layout (in ull elements)
#define WMD_OFF  (HC_ * 512)
#define PEXA_OFF (2 * HC_ * 512)
#define PEXB_OFF (2 * HC_ * 512 + NKG_ * HC_ * NQ_ * 2)
#define ULL_TOT  (2 * HC_ * 512 + 2 * NKG_ * HC_ * NQ_ * 2)
#define SMEM_BYTES (ULL_TOT * 8 + (48 + 48 + 48 + 48 + 16) * 4)

// ---------------- persistent wavefront kernel ----------------
__global__ void __launch_bounds__(NT_, 1) rnn_kernel(
    const float* __restrict__ W0,  const float* __restrict__ b0,
    const float* __restrict__ u0,  const float* __restrict__ g10,
    const float* __restrict__ be10,const float* __restrict__ g20,
    const float* __restrict__ be20,
    const float* __restrict__ Wm,  const float* __restrict__ bm,
    const float* __restrict__ um,  const float* __restrict__ g1m,
    const float* __restrict__ be1m,const float* __restrict__ g2m,
    const float* __restrict__ be2m,
    const float* __restrict__ Wfc, const float* __restrict__ bfc,
    float* __restrict__ out) {

    extern __shared__ __align__(16) char smraw[];
    ull*   W0d  = (ull*)smraw;                 // [8][512] (w,w)  32KB
    ull*   Wmd  = W0d + WMD_OFF;               // [8][512]        32KB
    ull*   pexA = W0d + PEXA_OFF;              // cell0 partials [16g][8c][32q][2]  64KB
    ull*   pexB = W0d + PEXB_OFF;              // cells 1/2 partials                64KB
    float* sfull = (float*)(W0d + ULL_TOT);    // 48
    float* scomb = sfull + 48;                 // 48
    float* p0    = scomb + 48;                 // [6][8]
    float* pm    = p0 + 48;                    // [6][8]
    float* shd   = pm + 48;                    // 16 (head reduce)

    const int tid   = threadIdx.x;
    const int q     = tid & 31;     // batch quad -> elems 4q..4q+3 (within half)
    const int g     = tid >> 5;     // k-group / warp id
    const int cg    = blockIdx.x >> 1;
    const int b     = blockIdx.x & 1;
    const int jbase = cg * HC_;
    const int be    = b * 128 + 4 * q;   // batch element base

    // reducer role: warps 0..11; cell e, column pair cp
    const int e  = g >> 2;          // valid if g < 12
    const int cp = g & 3;

    // Stage duplicated weights + params
    for (int idx = tid; idx < HC_ * 512; idx += NT_) {
        int c = idx >> 9, k = idx & 511;
        float w0 = W0[(size_t)(jbase + c) * D_ + k];
        float wm = Wm[(size_t)(jbase + c) * H_ + k];
        W0d[idx] = pk2(w0, w0);
        Wmd[idx] = pk2(wm, wm);
    }
    if (tid < HC_) {
        int j = jbase + tid;
        p0[0 * 8 + tid] = b0[j];  p0[1 * 8 + tid] = u0[j];
        p0[2 * 8 + tid] = g10[j]; p0[3 * 8 + tid] = be10[j];
        p0[4 * 8 + tid] = g20[j]; p0[5 * 8 + tid] = be20[j];
        pm[0 * 8 + tid] = bm[j];  pm[1 * 8 + tid] = um[j];
        pm[2 * 8 + tid] = g1m[j]; pm[3 * 8 + tid] = be1m[j];
        pm[4 * 8 + tid] = g2m[j]; pm[5 * 8 + tid] = be2m[j];
    }
    // Zero states + counters (per-launch; graph replays)
    for (int i = tid; i < 1024; i += NT_) {
        size_t o = (size_t)blockIdx.x * 1024 + i;
        __stcg(&d_h0 [0][o], 0.f); __stcg(&d_h0 [1][o], 0.f);
        __stcg(&d_hm0[0][o], 0.f); __stcg(&d_hm0[1][o], 0.f);
        __stcg(&d_hm1[o], 0.f);
    }
    if (blockIdx.x == 0 && tid < CG_) d_pcnt[tid] = 0u;
    __syncthreads();
    gsync();

    // ---- wavefront: step s computes L0(t=s), L1(s-1), L2(s-2) ----
    for (int s = 0; s < NS_; s++) {
        const int rd = (s + 1) & 1;
        const int wr = s & 1;
        const int tt = (s < T_) ? s : (T_ - 1);
        const int kb = g * KG_;

        // ======== pass 1: cell 0 GEMM (x @ W0^T) -> park in pexA ==========
        {
            const float* in0 = d_xT + ((size_t)tt * 512 + kb) * B_ + be;
            ull acc[HC_][2];
            #pragma unroll
            for (int c = 0; c < HC_; c++) { acc[c][0] = 0ull; acc[c][1] = 0ull; }
            #pragma unroll 2
            for (int kk = 0; kk < KG_; kk += 4) {
                ulonglong2 a[4];
                #pragma unroll
                for (int j = 0; j < 4; j++)
                    a[j] = __ldcg((const ulonglong2*)(in0 + (size_t)(kk + j) * B_));
                #pragma unroll
                for (int c = 0; c < HC_; c++) {
                    const ulonglong2* wp = (const ulonglong2*)(W0d + c * 512 + kb + kk);
                    ulonglong2 w01 = wp[0], w23 = wp[1];
                    fma2(acc[c][0], a[0].x, w01.x); fma2(acc[c][1], a[0].y, w01.x);
                    fma2(acc[c][0], a[1].x, w01.y); fma2(acc[c][1], a[1].y, w01.y);
                    fma2(acc[c][0], a[2].x, w23.x); fma2(acc[c][1], a[2].y, w23.x);
                    fma2(acc[c][0], a[3].x, w23.y); fma2(acc[c][1], a[3].y, w23.y);
                }
            }
            #pragma unroll
            for (int c = 0; c < HC_; c++) {
                ulonglong2 v; v.x = acc[c][0]; v.y = acc[c][1];
                ((ulonglong2*)pexA)[(g * HC_ + c) * NQ_ + q] = v;
            }
        }

        // ======== pass 2: cells 1 & 2 GEMM (shared Wm LDS) ================
        ull acc2[HC_][2];
        {
            const float* in1 = d_h0 [rd] + (size_t)kb * B_ + be;
            const float* in2 = d_hm0[rd] + (size_t)kb * B_ + be;
            ull acc1[HC_][2];
            #pragma unroll
            for (int c = 0; c < HC_; c++) {
                acc1[c][0] = 0ull; acc1[c][1] = 0ull;
                acc2[c][0] = 0ull; acc2[c][1] = 0ull;
            }
            #pragma unroll 2
            for (int kk = 0; kk < KG_; kk += 2) {
                ulonglong2 a1[2], a2[2];
                #pragma unroll
                for (int j = 0; j < 2; j++) {
                    a1[j] = __ldcg((const ulonglong2*)(in1 + (size_t)(kk + j) * B_));
                    a2[j] = __ldcg((const ulonglong2*)(in2 + (size_t)(kk + j) * B_));
                }
                #pragma unroll
                for (int c = 0; c < HC_; c++) {
                    ulonglong2 w = *(const ulonglong2*)(Wmd + c * 512 + kb + kk);
                    fma2(acc1[c][0], a1[0].x, w.x); fma2(acc1[c][1], a1[0].y, w.x);
                    fma2(acc1[c][0], a1[1].x, w.y); fma2(acc1[c][1], a1[1].y, w.y);
                    fma2(acc2[c][0], a2[0].x, w.x); fma2(acc2[c][1], a2[0].y, w.x);
                    fma2(acc2[c][0], a2[1].x, w.y); fma2(acc2[c][1], a2[1].y, w.y);
                }
            }
            // park cell1
            #pragma unroll
            for (int c = 0; c < HC_; c++) {
                ulonglong2 v; v.x = acc1[c][0]; v.y = acc1[c][1];
                ((ulonglong2*)pexB)[(g * HC_ + c) * NQ_ + q] = v;
            }
        }
        __syncthreads();   // pexA (cell0) + pexB (cell1) complete

        // ======== reducers: cells 0,1 k-reduction + BN1 stats =============
        float z[2][4];
        if (e < 2) {   // warps 0..7
            const ull* px = (e == 0) ? pexA : pexB;
            const float* prm = (e == 0) ? p0 : pm;
            float st[4];
            #pragma unroll
            for (int j = 0; j < 2; j++) {
                int c = 2 * cp + j;
                float bb = prm[0 * 8 + c];
                float f0 = bb, f1 = bb, f2 = bb, f3 = bb;
                #pragma unroll
                for (int gg = 0; gg < NKG_; gg++) {
                    ulonglong2 v = ((const ulonglong2*)px)[(gg * HC_ + c) * NQ_ + q];
                    float x0, x1, x2, x3;
                    upk2(x0, x1, v.x); upk2(x2, x3, v.y);
                    f0 += x0; f1 += x1; f2 += x2; f3 += x3;
                }
                z[j][0] = f0; z[j][1] = f1; z[j][2] = f2; z[j][3] = f3;
                st[2 * j]     = f0 + f1 + f2 + f3;
                st[2 * j + 1] = f0 * f0 + f1 * f1 + f2 * f2 + f3 * f3;
            }
            #pragma unroll
            for (int off = 16; off > 0; off >>= 1) {
                #pragma unroll
                for (int k4 = 0; k4 < 4; k4++) st[k4] += __shfl_down_sync(0xffffffffu, st[k4], off);
            }
            if (q == 0) {
                #pragma unroll
                for (int k4 = 0; k4 < 4; k4++) sfull[e * 16 + 4 * cp + k4] = st[k4];
            }
        }
        __syncthreads();   // cell1 reducers done reading pexB

        // park cell2 (all threads)
        #pragma unroll
        for (int c = 0; c < HC_; c++) {
            ulonglong2 v; v.x = acc2[c][0]; v.y = acc2[c][1];
            ((ulonglong2*)pexB)[(g * HC_ + c) * NQ_ + q] = v;
        }
        __syncthreads();

        if (e == 2 && g < 12) {   // warps 8..11
            float st[4];
            #pragma unroll
            for (int j = 0; j < 2; j++) {
                int c = 2 * cp + j;
                float bb = pm[0 * 8 + c];
                float f0 = bb, f1 = bb, f2 = bb, f3 = bb;
                #pragma unroll
                for (int gg = 0; gg < NKG_; gg++) {
                    ulonglong2 v = ((const ulonglong2*)pexB)[(gg * HC_ + c) * NQ_ + q];
                    float x0, x1, x2, x3;
                    upk2(x0, x1, v.x); upk2(x2, x3, v.y);
                    f0 += x0; f1 += x1; f2 += x2; f3 += x3;
                }
                z[j][0] = f0; z[j][1] = f1; z[j][2] = f2; z[j][3] = f3;
                st[2 * j]     = f0 + f1 + f2 + f3;
                st[2 * j + 1] = f0 * f0 + f1 * f1 + f2 * f2 + f3 * f3;
            }
            #pragma unroll
            for (int off = 16; off > 0; off >>= 1) {
                #pragma unroll
                for (int k4 = 0; k4 < 4; k4++) st[k4] += __shfl_down_sync(0xffffffffu, st[k4], off);
            }
            if (q == 0) {
                #pragma unroll
                for (int k4 = 0; k4 < 4; k4++) sfull[2 * 16 + 4 * cp + k4] = st[k4];
            }
        }

        // ======== BN1 exchange ============================================
        stats_exchange(0, 4u * s + 2u, cg, b, sfull, scomb);

        // ======== BN1 apply + recurrence + relu + BN2 stats ===============
        float y[2][4];
        if (g < 12) {
            const float* prm = (e == 0) ? p0 : pm;
            const float* hb = (e == 0) ? d_h0[rd] : (e == 1) ? d_hm0[rd] : d_hm1;
            float st[4];
            #pragma unroll
            for (int j = 0; j < 2; j++) {
                int c = 2 * cp + j;
                float m   = scomb[e * 16 + 4 * cp + 2 * j] * (1.f / B_);
                float var = scomb[e * 16 + 4 * cp + 2 * j + 1] * (1.f / B_) - m * m;
                float rs  = rsqrtf(var + EPS_);
                float g1 = prm[2 * 8 + c], be1 = prm[3 * 8 + c], u = prm[1 * 8 + c];
                float4 hv = make_float4(0.f, 0.f, 0.f, 0.f);
                if (s != e) hv = __ldcg((const float4*)(hb + (size_t)(jbase + c) * B_ + be));
                y[j][0] = fmaxf(fmaf(hv.x, u, (z[j][0] - m) * rs * g1 + be1), 0.f);
                y[j][1] = fmaxf(fmaf(hv.y, u, (z[j][1] - m) * rs * g1 + be1), 0.f);
                y[j][2] = fmaxf(fmaf(hv.z, u, (z[j][2] - m) * rs * g1 + be1), 0.f);
                y[j][3] = fmaxf(fmaf(hv.w, u, (z[j][3] - m) * rs * g1 + be1), 0.f);
                st[2 * j]     = y[j][0] + y[j][1] + y[j][2] + y[j][3];
                st[2 * j + 1] = y[j][0] * y[j][0] + y[j][1] * y[j][1] +
                                y[j][2] * y[j][2] + y[j][3] * y[j][3];
            }
            #pragma unroll
            for (int off = 16; off > 0; off >>= 1) {
                #pragma unroll
                for (int k4 = 0; k4 < 4; k4++) st[k4] += __shfl_down_sync(0xffffffffu, st[k4], off);
            }
            if (q == 0) {
                #pragma unroll
                for (int k4 = 0; k4 < 4; k4++) sfull[e * 16 + 4 * cp + k4] = st[k4];
            }
        }

        // ======== BN2 exchange ============================================
        stats_exchange(1, 4u * s + 4u, cg, b, sfull, scomb);

        // ======== BN2 apply + publish state ================================
        const bool act = (e == 0) ? (s < T_)
                       : (e == 1) ? (s >= 1 && s <= T_)
                                  : (s >= 2);
        if (g < 12 && act) {
            const float* prm = (e == 0) ? p0 : pm;
            float* ob = (e == 0) ? d_h0[wr] : (e == 1) ? d_hm0[wr] : d_hm1;
            #pragma unroll
            for (int j = 0; j < 2; j++) {
                int c = 2 * cp + j;
                float m   = scomb[e * 16 + 4 * cp + 2 * j] * (1.f / B_);
                float var = scomb[e * 16 + 4 * cp + 2 * j + 1] * (1.f / B_) - m * m;
                float rs  = rsqrtf(var + EPS_);
                float g2 = prm[4 * 8 + c], be2 = prm[5 * 8 + c];
                float4 o;
                o.x = (y[j][0] - m) * rs * g2 + be2;
                o.y = (y[j][1] - m) * rs * g2 + be2;
                o.z = (y[j][2] - m) * rs * g2 + be2;
                o.w = (y[j][3] - m) * rs * g2 + be2;
                __stcg((float4*)(ob + (size_t)(jbase + c) * B_ + be), o);
            }
        }

        gsync();
    }

    // ---- head: logits + log_softmax (2 batch rows per CTA) ----
    float* hrow = (float*)pexA;
    for (int rr = 0; rr < 2; rr++) {
        int r = blockIdx.x * 2 + rr;
        __syncthreads();
        for (int j = tid; j < H_; j += NT_) hrow[j] = __ldcg(&d_hm1[(size_t)j * B_ + r]);
        __syncthreads();

        float acc = -INFINITY;
        if (tid < O_) {
            acc = bfc[tid];
            const float4* wrow = (const float4*)(Wfc + (size_t)tid * H_);
            #pragma unroll 4
            for (int j4 = 0; j4 < H_ / 4; j4++) {
                float4 w = wrow[j4];
                acc = fmaf(hrow[4 * j4 + 0], w.x, acc);
                acc = fmaf(hrow[4 * j4 + 1], w.y, acc);
                acc = fmaf(hrow[4 * j4 + 2], w.z, acc);
                acc = fmaf(hrow[4 * j4 + 3], w.w, acc);
            }
        }
        float mx = block_allreduce_max(acc, shd);
        float ev = (tid < O_) ? expf(acc - mx) : 0.f;
        float se = block_allreduce_sum(ev, shd);
        if (tid < O_) out[(size_t)r * O_ + tid] = acc - mx - logf(se);
    }
}

// ---------------- harness entry ----------------
extern "C" void kernel_launch(void* const* d_in, const int* in_sizes, int n_in,
                              void* d_out, int out_size) {
    (void)in_sizes; (void)n_in; (void)out_size;
    const float* x    = (const float*)d_in[0];
    const float* W0   = (const float*)d_in[1];
    const float* b0   = (const float*)d_in[2];
    const float* u0   = (const float*)d_in[3];
    const float* g10  = (const float*)d_in[4];
    const float* be10 = (const float*)d_in[5];
    const float* g20  = (const float*)d_in[6];
    const float* be20 = (const float*)d_in[7];
    const float* Wm   = (const float*)d_in[8];
    const float* bm   = (const float*)d_in[9];
    const float* um   = (const float*)d_in[10];
    const float* g1m  = (const float*)d_in[11];
    const float* be1m = (const float*)d_in[12];
    const float* g2m  = (const float*)d_in[13];
    const float* be2m = (const float*)d_in[14];
    const float* Wfc  = (const float*)d_in[15];
    const float* bfc  = (const float*)d_in[16];
    float* out = (float*)d_out;

    static int attr_set = 0;
    if (!attr_set) {
        cudaFuncSetAttribute(rnn_kernel,
                             cudaFuncAttributeMaxDynamicSharedMemorySize, SMEM_BYTES);
        attr_set = 1;
    }

    transpose_kernel<<<dim3(T_, D_ / 32, B_ / 32), dim3(32, 32)>>>(x);
    rnn_kernel<<<G_, NT_, SMEM_BYTES>>>(W0, b0, u0, g10, be10, g20, be20,
                                        Wm, bm, um, g1m, be1m, g2m, be2m,
                                        Wfc, bfc, out);
}

// round 8
// speedup vs baseline: 1.6022x; 1.6022x over previous
#include <cuda_runtime.h>
#include <math.h>

#define B_   256
#define T_   256
#define D_   512
#define H_   512
#define O_   256
#define EPS_ 1e-5f

#define TJ_  64    // j-tile per GEMM CTA
#define TK_  64    // k-tile
#define GT_  256   // GEMM threads per CTA

typedef unsigned long long ull;

// ---------------- static device scratch ----------------
__device__ float d_xT  [(size_t)T_ * D_ * B_];   // x transposed: [t][k][i]
__device__ float d_bufA[(size_t)T_ * H_ * B_];   // Z buffers [t][j][i]
__device__ float d_bufB[(size_t)T_ * H_ * B_];   // H buffers [t][j][i]

// ---------------- packed f32x2 helpers ----------------
__device__ __forceinline__ ull pk2(float x, float y) {
    ull r; asm("mov.b64 %0, {%1, %2};" : "=l"(r) : "f"(x), "f"(y)); return r;
}
__device__ __forceinline__ void upk2(float& x, float& y, ull v) {
    asm("mov.b64 {%0, %1}, %2;" : "=f"(x), "=f"(y) : "l"(v));
}
__device__ __forceinline__ void fma2(ull& d, ull a, ull b) {
    asm("fma.rn.f32x2 %0, %1, %2, %0;" : "+l"(d) : "l"(a), "l"(b));
}

// ---------------- transpose x: [B][T][D] -> [T][D][B] ----------------
__global__ void transpose_kernel(const float* __restrict__ x) {
    __shared__ float sm[32][33];
    int t  = blockIdx.x;
    int k0 = blockIdx.y * 32;
    int i0 = blockIdx.z * 32;
    int tx = threadIdx.x, ty = threadIdx.y;
    sm[ty][tx] = x[((size_t)(i0 + ty) * T_ + t) * D_ + (k0 + tx)];
    __syncthreads();
    d_xT[((size_t)t * D_ + (k0 + ty)) * B_ + (i0 + tx)] = sm[tx][ty];
}

// ---------------- GEMM + fused BN1 ----------------
// OUT[t][j][i] = BN1_over_i( sum_k W[j][k] * IN[t][k][i] + bias[j] )
// grid (T_, H_/TJ_), block 256.
// Thread: warp jq = tid>>5 owns 8 j's; lane ip = tid&31 owns i-pairs
// {ip, ip+32, ip+64, ip+96} -> each warp covers the FULL batch for its j's,
// so BN1 stats are a pure warp shuffle reduction.
#define GEMM_SMEM (TK_ * B_ * 4 + TK_ * TJ_ * 8)

__global__ void __launch_bounds__(GT_, 2) gemm_bn_kernel(
    const float* __restrict__ IN, const float* __restrict__ W,
    const float* __restrict__ bias, const float* __restrict__ gam,
    const float* __restrict__ bet, float* __restrict__ OUT) {

    extern __shared__ __align__(16) char smraw[];
    float* Xs = (float*)smraw;                 // [TK_][256] floats, 64KB
    ull*   Ws = (ull*)(smraw + TK_ * B_ * 4);  // [TK_][TJ_] (w,w), 32KB

    const int t   = blockIdx.x;
    const int j0  = blockIdx.y * TJ_;
    const int tid = threadIdx.x;
    const int jq  = tid >> 5;     // warp -> j octet
    const int ip  = tid & 31;     // lane -> i pairs {ip+32q}

    const float* inT = IN + (size_t)t * 512 * 256;

    ull acc[8][4];
    #pragma unroll
    for (int jj = 0; jj < 8; jj++)
        #pragma unroll
        for (int q = 0; q < 4; q++) acc[jj][q] = 0ull;

    const int jl = tid >> 2;      // W-stage: row
    const int kq = tid & 3;       // W-stage: col quarter

    for (int kt = 0; kt < 512; kt += TK_) {
        __syncthreads();          // previous tile fully consumed
        // stage X tile [TK_][256]: coalesced float4
        #pragma unroll
        for (int it = 0; it < 16; it++) {
            int idx = it * GT_ + tid;
            int r = idx >> 6, c4 = idx & 63;
            ((float4*)(Xs + r * 256))[c4] =
                ((const float4*)(inT + (size_t)(kt + r) * 256))[c4];
        }
        // stage W tile transposed + duplicated: Ws[k][j] = (w,w)
        #pragma unroll
        for (int m = 0; m < 4; m++) {
            int kc = 4 * kq + 16 * m;     // k offset of this float4
            float4 wv = *(const float4*)(W + (size_t)(j0 + jl) * 512 + kt + kc);
            Ws[(kc + 0) * TJ_ + jl] = pk2(wv.x, wv.x);
            Ws[(kc + 1) * TJ_ + jl] = pk2(wv.y, wv.y);
            Ws[(kc + 2) * TJ_ + jl] = pk2(wv.z, wv.z);
            Ws[(kc + 3) * TJ_ + jl] = pk2(wv.w, wv.w);
        }
        __syncthreads();
        // compute
        #pragma unroll 2
        for (int k = 0; k < TK_; k++) {
            const float* xr = Xs + k * 256;
            ull xv0 = *(const ull*)(xr + 2 * ip);
            ull xv1 = *(const ull*)(xr + 2 * ip + 64);
            ull xv2 = *(const ull*)(xr + 2 * ip + 128);
            ull xv3 = *(const ull*)(xr + 2 * ip + 192);
            const ulonglong2* wr = (const ulonglong2*)(Ws + k * TJ_ + jq * 8);
            ulonglong2 wa = wr[0], wb = wr[1], wc = wr[2], wd = wr[3];
            fma2(acc[0][0], xv0, wa.x); fma2(acc[0][1], xv1, wa.x);
            fma2(acc[0][2], xv2, wa.x); fma2(acc[0][3], xv3, wa.x);
            fma2(acc[1][0], xv0, wa.y); fma2(acc[1][1], xv1, wa.y);
            fma2(acc[1][2], xv2, wa.y); fma2(acc[1][3], xv3, wa.y);
            fma2(acc[2][0], xv0, wb.x); fma2(acc[2][1], xv1, wb.x);
            fma2(acc[2][2], xv2, wb.x); fma2(acc[2][3], xv3, wb.x);
            fma2(acc[3][0], xv0, wb.y); fma2(acc[3][1], xv1, wb.y);
            fma2(acc[3][2], xv2, wb.y); fma2(acc[3][3], xv3, wb.y);
            fma2(acc[4][0], xv0, wc.x); fma2(acc[4][1], xv1, wc.x);
            fma2(acc[4][2], xv2, wc.x); fma2(acc[4][3], xv3, wc.x);
            fma2(acc[5][0], xv0, wc.y); fma2(acc[5][1], xv1, wc.y);
            fma2(acc[5][2], xv2, wc.y); fma2(acc[5][3], xv3, wc.y);
            fma2(acc[6][0], xv0, wd.x); fma2(acc[6][1], xv1, wd.x);
            fma2(acc[6][2], xv2, wd.x); fma2(acc[6][3], xv3, wd.x);
            fma2(acc[7][0], xv0, wd.y); fma2(acc[7][1], xv1, wd.y);
            fma2(acc[7][2], xv2, wd.y); fma2(acc[7][3], xv3, wd.y);
        }
    }

    // ---- epilogue: bias + BN1 per j (warp-local stats), store ----
    #pragma unroll
    for (int jj = 0; jj < 8; jj++) {
        int j = j0 + jq * 8 + jj;
        float bb = bias[j];
        float z[8];
        #pragma unroll
        for (int q = 0; q < 4; q++) {
            float a, b2;
            upk2(a, b2, acc[jj][q]);
            z[2 * q] = a + bb; z[2 * q + 1] = b2 + bb;
        }
        float s1 = 0.f, s2 = 0.f;
        #pragma unroll
        for (int q = 0; q < 8; q++) { s1 += z[q]; s2 += z[q] * z[q]; }
        #pragma unroll
        for (int off = 16; off > 0; off >>= 1) {
            s1 += __shfl_xor_sync(0xffffffffu, s1, off);
            s2 += __shfl_xor_sync(0xffffffffu, s2, off);
        }
        float m   = s1 * (1.f / B_);
        float var = s2 * (1.f / B_) - m * m;
        float sc  = rsqrtf(var + EPS_) * gam[j];
        float sh  = bet[j] - m * sc;
        float* op = OUT + ((size_t)t * 512 + j) * 256;
        #pragma unroll
        for (int q = 0; q < 4; q++) {
            float ox = z[2 * q] * sc + sh;
            float oy = z[2 * q + 1] * sc + sh;
            *(ull*)(op + 2 * (ip + 32 * q)) = pk2(ox, oy);
        }
    }
}

// ---------------- sequential state scan (CTA-local BN2) ----------------
// h(t) = BN2_over_i( relu(Z[t] + h(t-1) * u) );  OUT[t] = h(t)
// grid 128, block 512: col group g = tid>>7 (4 cols/CTA), pair p = tid&127.
__global__ void __launch_bounds__(512) scan_kernel(
    const float* __restrict__ Z, const float* __restrict__ u,
    const float* __restrict__ g2, const float* __restrict__ be2,
    float* __restrict__ OUT) {

    __shared__ float sred[2][4][4][2];   // [t&1][col][warp][stat]

    const int tid = threadIdx.x;
    const int g   = tid >> 7;
    const int p   = tid & 127;
    const int wg  = (tid >> 5) & 3;
    const int lane = tid & 31;
    const int j   = blockIdx.x * 4 + g;
    const size_t base = (size_t)j * 256 + 2 * p;
    const size_t tstr = (size_t)512 * 256;

    const float uv = u[j], gv = g2[j], bv = be2[j];
    float hx = 0.f, hy = 0.f;

    ull zn0 = *(const ull*)(Z + base);
    ull zn1 = *(const ull*)(Z + tstr + base);

    for (int t = 0; t < T_; t++) {
        float zx, zy;
        upk2(zx, zy, zn0);
        zn0 = zn1;
        if (t + 2 < T_) zn1 = *(const ull*)(Z + (size_t)(t + 2) * tstr + base);

        float yx = fmaxf(fmaf(hx, uv, zx), 0.f);
        float yy = fmaxf(fmaf(hy, uv, zy), 0.f);
        float s1 = yx + yy, s2 = yx * yx + yy * yy;
        #pragma unroll
        for (int off = 16; off > 0; off >>= 1) {
            s1 += __shfl_down_sync(0xffffffffu, s1, off);
            s2 += __shfl_down_sync(0xffffffffu, s2, off);
        }
        if (lane == 0) { sred[t & 1][g][wg][0] = s1; sred[t & 1][g][wg][1] = s2; }
        __syncthreads();
        float fs1 = sred[t & 1][g][0][0] + sred[t & 1][g][1][0] +
                    sred[t & 1][g][2][0] + sred[t & 1][g][3][0];
        float fs2 = sred[t & 1][g][0][1] + sred[t & 1][g][1][1] +
                    sred[t & 1][g][2][1] + sred[t & 1][g][3][1];
        float m   = fs1 * (1.f / B_);
        float var = fs2 * (1.f / B_) - m * m;
        float sc  = rsqrtf(var + EPS_) * gv;
        float sh  = bv - m * sc;
        hx = yx * sc + sh;
        hy = yy * sc + sh;
        *(ull*)(OUT + (size_t)t * tstr + base) = pk2(hx, hy);
    }
}

// ---------------- head: logits + log_softmax ----------------
// grid 256 (batch row), block 256 (output class)
__global__ void __launch_bounds__(256) head_kernel(
    const float* __restrict__ HM,   // [j][i] slice (t = T-1)
    const float* __restrict__ Wfc, const float* __restrict__ bfc,
    float* __restrict__ out) {

    __shared__ float hrow[H_];
    __shared__ float shd[8];

    const int r   = blockIdx.x;
    const int tid = threadIdx.x;

    hrow[tid]       = HM[(size_t)tid * 256 + r];
    hrow[tid + 256] = HM[(size_t)(tid + 256) * 256 + r];
    __syncthreads();

    float acc = bfc[tid];
    const float4* wrow = (const float4*)(Wfc + (size_t)tid * H_);
    #pragma unroll 4
    for (int j4 = 0; j4 < H_ / 4; j4++) {
        float4 w = wrow[j4];
        acc = fmaf(hrow[4 * j4 + 0], w.x, acc);
        acc = fmaf(hrow[4 * j4 + 1], w.y, acc);
        acc = fmaf(hrow[4 * j4 + 2], w.z, acc);
        acc = fmaf(hrow[4 * j4 + 3], w.w, acc);
    }

    // block max
    float v = acc;
    #pragma unroll
    for (int off = 16; off > 0; off >>= 1)
        v = fmaxf(v, __shfl_xor_sync(0xffffffffu, v, off));
    if ((tid & 31) == 0) shd[tid >> 5] = v;
    __syncthreads();
    float mx = shd[0];
    #pragma unroll
    for (int w = 1; w < 8; w++) mx = fmaxf(mx, shd[w]);
    __syncthreads();

    // block sum of exp
    float e = expf(acc - mx);
    float sv = e;
    #pragma unroll
    for (int off = 16; off > 0; off >>= 1)
        sv += __shfl_xor_sync(0xffffffffu, sv, off);
    if ((tid & 31) == 0) shd[tid >> 5] = sv;
    __syncthreads();
    float se = 0.f;
    #pragma unroll
    for (int w = 0; w < 8; w++) se += shd[w];

    out[(size_t)r * O_ + tid] = acc - mx - logf(se);
}

// ---------------- harness entry ----------------
extern "C" void kernel_launch(void* const* d_in, const int* in_sizes, int n_in,
                              void* d_out, int out_size) {
    (void)in_sizes; (void)n_in; (void)out_size;
    const float* x    = (const float*)d_in[0];
    const float* W0   = (const float*)d_in[1];
    const float* b0   = (const float*)d_in[2];
    const float* u0   = (const float*)d_in[3];
    const float* g10  = (const float*)d_in[4];
    const float* be10 = (const float*)d_in[5];
    const float* g20  = (const float*)d_in[6];
    const float* be20 = (const float*)d_in[7];
    const float* Wm   = (const float*)d_in[8];
    const float* bm   = (const float*)d_in[9];
    const float* um   = (const float*)d_in[10];
    const float* g1m  = (const float*)d_in[11];
    const float* be1m = (const float*)d_in[12];
    const float* g2m  = (const float*)d_in[13];
    const float* be2m = (const float*)d_in[14];
    const float* Wfc  = (const float*)d_in[15];
    const float* bfc  = (const float*)d_in[16];
    float* out = (float*)d_out;

    static int attr_set = 0;
    if (!attr_set) {
        cudaFuncSetAttribute(gemm_bn_kernel,
                             cudaFuncAttributeMaxDynamicSharedMemorySize, GEMM_SMEM);
        attr_set = 1;
    }

    float* bufA;  cudaGetSymbolAddress((void**)&bufA, d_bufA);
    float* bufB;  cudaGetSymbolAddress((void**)&bufB, d_bufB);
    float* xT;    cudaGetSymbolAddress((void**)&xT,   d_xT);

    // x -> xT
    transpose_kernel<<<dim3(T_, D_ / 32, B_ / 32), dim3(32, 32)>>>(x);
    // layer 0
    gemm_bn_kernel<<<dim3(T_, H_ / TJ_), GT_, GEMM_SMEM>>>(xT, W0, b0, g10, be10, bufA);
    scan_kernel<<<128, 512>>>(bufA, u0, g20, be20, bufB);
    // middle layer 1
    gemm_bn_kernel<<<dim3(T_, H_ / TJ_), GT_, GEMM_SMEM>>>(bufB, Wm, bm, g1m, be1m, bufA);
    scan_kernel<<<128, 512>>>(bufA, um, g2m, be2m, bufB);
    // middle layer 2
    gemm_bn_kernel<<<dim3(T_, H_ / TJ_), GT_, GEMM_SMEM>>>(bufB, Wm, bm, g1m, be1m, bufA);
    scan_kernel<<<128, 512>>>(bufA, um, g2m, be2m, bufB);
    // head on final hm1 slice
    head_kernel<<<O_, 256>>>(bufB + (size_t)(T_ - 1) * H_ * B_, Wfc, bfc, out);
}

// round 10
// speedup vs baseline: 1.7515x; 1.0931x over previous
#include <cuda_runtime.h>
#include <cstdint>
#include <math.h>

#define B_   256
#define T_   256
#define D_   512
#define H_   512
#define O_   256
#define EPS_ 1e-5f

#define TJ_  64    // j-tile per GEMM CTA
#define TK_  32    // k-tile (double buffered)
#define GT_  256   // GEMM threads per CTA
#define NTILE_ (512 / TK_)

typedef unsigned long long ull;

// ---------------- static device scratch ----------------
__device__ float d_xT  [(size_t)T_ * D_ * B_];   // x transposed: [t][k][i]
__device__ float d_bufA[(size_t)T_ * H_ * B_];   // Z buffers [t][j][i]
__device__ float d_bufB[(size_t)T_ * H_ * B_];   // H buffers [t][j][i]

// ---------------- packed f32x2 helpers ----------------
__device__ __forceinline__ ull pk2(float x, float y) {
    ull r; asm("mov.b64 %0, {%1, %2};" : "=l"(r) : "f"(x), "f"(y)); return r;
}
__device__ __forceinline__ void upk2(float& x, float& y, ull v) {
    asm("mov.b64 {%0, %1}, %2;" : "=f"(x), "=f"(y) : "l"(v));
}
__device__ __forceinline__ void fma2(ull& d, ull a, ull b) {
    asm("fma.rn.f32x2 %0, %1, %2, %0;" : "+l"(d) : "l"(a), "l"(b));
}
__device__ __forceinline__ void cp_async16(unsigned saddr, const void* gaddr) {
    asm volatile("cp.async.cg.shared.global [%0], [%1], 16;"
                 :: "r"(saddr), "l"(gaddr));
}
#define CP_COMMIT() asm volatile("cp.async.commit_group;")
#define CP_WAIT0()  asm volatile("cp.async.wait_group 0;")

// ---------------- transpose x: [B][T][D] -> [T][D][B] ----------------
__global__ void transpose_kernel(const float* __restrict__ x) {
    __shared__ float sm[32][33];
    int t  = blockIdx.x;
    int k0 = blockIdx.y * 32;
    int i0 = blockIdx.z * 32;
    int tx = threadIdx.x, ty = threadIdx.y;
    sm[ty][tx] = x[((size_t)(i0 + ty) * T_ + t) * D_ + (k0 + tx)];
    __syncthreads();
    d_xT[((size_t)t * D_ + (k0 + ty)) * B_ + (i0 + tx)] = sm[tx][ty];
}

// ---------------- GEMM + fused BN1 (cp.async double-buffered) ----------------
// OUT[t][j][i] = BN1_over_i( sum_k W[j][k] * IN[t][k][i] + bias[j] )
// grid (T_, H_/TJ_), block 256. Warp jq owns 8 j's; lane ip owns i-pairs
// {ip+32q, q<4} -> warp covers full batch -> BN1 = warp shuffle reduction.
#define STAGE_BYTES (TK_ * B_ * 4 + TK_ * TJ_ * 8)   // 32KB X + 16KB W = 48KB
#define GEMM_SMEM   (2 * STAGE_BYTES)                 // 96KB

__global__ void __launch_bounds__(GT_, 2) gemm_bn_kernel(
    const float* __restrict__ IN, const float* __restrict__ W,
    const float* __restrict__ bias, const float* __restrict__ gam,
    const float* __restrict__ bet, float* __restrict__ OUT) {

    extern __shared__ __align__(16) char smraw[];
    const int t   = blockIdx.x;
    const int j0  = blockIdx.y * TJ_;
    const int tid = threadIdx.x;
    const int jq  = tid >> 5;     // warp -> j octet
    const int ip  = tid & 31;     // lane -> i pairs {ip+32q}
    const int jl  = tid >> 2;     // W-stage row (0..63)
    const int kq  = tid & 3;      // W-stage k octet (k = 8*kq..8*kq+7)

    float* Xs[2] = { (float*)smraw, (float*)(smraw + STAGE_BYTES) };
    ull*   Ws[2] = { (ull*)(smraw + TK_ * B_ * 4),
                     (ull*)(smraw + STAGE_BYTES + TK_ * B_ * 4) };
    unsigned xsa[2] = { (unsigned)__cvta_generic_to_shared(Xs[0]),
                        (unsigned)__cvta_generic_to_shared(Xs[1]) };

    const float* inT = IN + (size_t)t * 512 * 256;
    const float* wrow = W + (size_t)(j0 + jl) * 512 + 8 * kq;

    ull acc[8][4];
    #pragma unroll
    for (int jj = 0; jj < 8; jj++)
        #pragma unroll
        for (int q = 0; q < 4; q++) acc[jj][q] = 0ull;

    // --- preamble: stage tile 0 ---
    #pragma unroll
    for (int m = 0; m < 8; m++) {
        int idx = m * GT_ + tid;
        int r = idx >> 6, c = idx & 63;
        cp_async16(xsa[0] + (unsigned)(r * 1024 + c * 16),
                   inT + (size_t)r * 256 + c * 4);
    }
    CP_COMMIT();
    float4 wr0 = *(const float4*)(wrow);
    float4 wr1 = *(const float4*)(wrow + 4);
    CP_WAIT0();
    {
        ull* wd = Ws[0] + (8 * kq) * TJ_ + jl;
        wd[0 * TJ_] = pk2(wr0.x, wr0.x); wd[1 * TJ_] = pk2(wr0.y, wr0.y);
        wd[2 * TJ_] = pk2(wr0.z, wr0.z); wd[3 * TJ_] = pk2(wr0.w, wr0.w);
        wd[4 * TJ_] = pk2(wr1.x, wr1.x); wd[5 * TJ_] = pk2(wr1.y, wr1.y);
        wd[6 * TJ_] = pk2(wr1.z, wr1.z); wd[7 * TJ_] = pk2(wr1.w, wr1.w);
    }
    __syncthreads();

    // --- pipelined tile loop ---
    for (int it = 0; it < NTILE_; it++) {
        const int cur = it & 1, nxt = cur ^ 1;
        const int ktn = (it + 1) * TK_;
        if (it + 1 < NTILE_) {
            #pragma unroll
            for (int m = 0; m < 8; m++) {
                int idx = m * GT_ + tid;
                int r = idx >> 6, c = idx & 63;
                cp_async16(xsa[nxt] + (unsigned)(r * 1024 + c * 16),
                           inT + (size_t)(ktn + r) * 256 + c * 4);
            }
            CP_COMMIT();
            wr0 = *(const float4*)(wrow + ktn);
            wr1 = *(const float4*)(wrow + ktn + 4);
        }

        // compute on cur
        const float* xb = Xs[cur];
        const ull*   wb = Ws[cur] + jq * 8;
        #pragma unroll 4
        for (int k = 0; k < TK_; k++) {
            const float* xr = xb + k * 256;
            ull xv0 = *(const ull*)(xr + 2 * ip);
            ull xv1 = *(const ull*)(xr + 2 * ip + 64);
            ull xv2 = *(const ull*)(xr + 2 * ip + 128);
            ull xv3 = *(const ull*)(xr + 2 * ip + 192);
            const ulonglong2* wr = (const ulonglong2*)(wb + k * TJ_);
            ulonglong2 wa = wr[0], wbb = wr[1], wc = wr[2], wd = wr[3];
            fma2(acc[0][0], xv0, wa.x);  fma2(acc[0][1], xv1, wa.x);
            fma2(acc[0][2], xv2, wa.x);  fma2(acc[0][3], xv3, wa.x);
            fma2(acc[1][0], xv0, wa.y);  fma2(acc[1][1], xv1, wa.y);
            fma2(acc[1][2], xv2, wa.y);  fma2(acc[1][3], xv3, wa.y);
            fma2(acc[2][0], xv0, wbb.x); fma2(acc[2][1], xv1, wbb.x);
            fma2(acc[2][2], xv2, wbb.x); fma2(acc[2][3], xv3, wbb.x);
            fma2(acc[3][0], xv0, wbb.y); fma2(acc[3][1], xv1, wbb.y);
            fma2(acc[3][2], xv2, wbb.y); fma2(acc[3][3], xv3, wbb.y);
            fma2(acc[4][0], xv0, wc.x);  fma2(acc[4][1], xv1, wc.x);
            fma2(acc[4][2], xv2, wc.x);  fma2(acc[4][3], xv3, wc.x);
            fma2(acc[5][0], xv0, wc.y);  fma2(acc[5][1], xv1, wc.y);
            fma2(acc[5][2], xv2, wc.y);  fma2(acc[5][3], xv3, wc.y);
            fma2(acc[6][0], xv0, wd.x);  fma2(acc[6][1], xv1, wd.x);
            fma2(acc[6][2], xv2, wd.x);  fma2(acc[6][3], xv3, wd.x);
            fma2(acc[7][0], xv0, wd.y);  fma2(acc[7][1], xv1, wd.y);
            fma2(acc[7][2], xv2, wd.y);  fma2(acc[7][3], xv3, wd.y);
        }

        if (it + 1 < NTILE_) {
            ull* wd2 = Ws[nxt] + (8 * kq) * TJ_ + jl;
            wd2[0 * TJ_] = pk2(wr0.x, wr0.x); wd2[1 * TJ_] = pk2(wr0.y, wr0.y);
            wd2[2 * TJ_] = pk2(wr0.z, wr0.z); wd2[3 * TJ_] = pk2(wr0.w, wr0.w);
            wd2[4 * TJ_] = pk2(wr1.x, wr1.x); wd2[5 * TJ_] = pk2(wr1.y, wr1.y);
            wd2[6 * TJ_] = pk2(wr1.z, wr1.z); wd2[7 * TJ_] = pk2(wr1.w, wr1.w);
        }
        CP_WAIT0();
        __syncthreads();
    }

    // ---- epilogue: bias + BN1 per j (warp-local stats), store ----
    #pragma unroll
    for (int jj = 0; jj < 8; jj++) {
        int j = j0 + jq * 8 + jj;
        float bb = bias[j];
        float z[8];
        #pragma unroll
        for (int q = 0; q < 4; q++) {
            float a, b2;
            upk2(a, b2, acc[jj][q]);
            z[2 * q] = a + bb; z[2 * q + 1] = b2 + bb;
        }
        float s1 = 0.f, s2 = 0.f;
        #pragma unroll
        for (int q = 0; q < 8; q++) { s1 += z[q]; s2 += z[q] * z[q]; }
        #pragma unroll
        for (int off = 16; off > 0; off >>= 1) {
            s1 += __shfl_xor_sync(0xffffffffu, s1, off);
            s2 += __shfl_xor_sync(0xffffffffu, s2, off);
        }
        float m   = s1 * (1.f / B_);
        float var = s2 * (1.f / B_) - m * m;
        float sc  = rsqrtf(var + EPS_) * gam[j];
        float sh  = bet[j] - m * sc;
        float* op = OUT + ((size_t)t * 512 + j) * 256;
        #pragma unroll
        for (int q = 0; q < 4; q++) {
            float ox = z[2 * q] * sc + sh;
            float oy = z[2 * q + 1] * sc + sh;
            *(ull*)(op + 2 * (ip + 32 * q)) = pk2(ox, oy);
        }
    }
}

// ---------------- sequential state scan: warp-per-column, no block syncs ----
// h(t) = BN2_over_i( relu(Z[t] + h(t-1) * u) );  OUT[t] = h(t)
// grid 128, block 128: warp w owns column j = blockIdx*4 + w,
// lane owns batch elems 8*lane .. 8*lane+7.
__global__ void __launch_bounds__(128) scan_kernel(
    const float* __restrict__ Z, const float* __restrict__ u,
    const float* __restrict__ g2, const float* __restrict__ be2,
    float* __restrict__ OUT) {

    const int tid  = threadIdx.x;
    const int w    = tid >> 5;
    const int lane = tid & 31;
    const int j    = blockIdx.x * 4 + w;
    const size_t base = (size_t)j * 256 + 8 * lane;
    const size_t tstr = (size_t)512 * 256;

    const float uv = u[j], gv = g2[j], bv = be2[j];
    float h[8];
    #pragma unroll
    for (int q = 0; q < 8; q++) h[q] = 0.f;

    float4 zc0 = *(const float4*)(Z + base);
    float4 zc1 = *(const float4*)(Z + base + 4);
    float4 zn0 = *(const float4*)(Z + tstr + base);
    float4 zn1 = *(const float4*)(Z + tstr + base + 4);

    for (int t = 0; t < T_; t++) {
        float y[8];
        y[0] = fmaxf(fmaf(h[0], uv, zc0.x), 0.f);
        y[1] = fmaxf(fmaf(h[1], uv, zc0.y), 0.f);
        y[2] = fmaxf(fmaf(h[2], uv, zc0.z), 0.f);
        y[3] = fmaxf(fmaf(h[3], uv, zc0.w), 0.f);
        y[4] = fmaxf(fmaf(h[4], uv, zc1.x), 0.f);
        y[5] = fmaxf(fmaf(h[5], uv, zc1.y), 0.f);
        y[6] = fmaxf(fmaf(h[6], uv, zc1.z), 0.f);
        y[7] = fmaxf(fmaf(h[7], uv, zc1.w), 0.f);

        zc0 = zn0; zc1 = zn1;
        if (t + 2 < T_) {
            zn0 = *(const float4*)(Z + (size_t)(t + 2) * tstr + base);
            zn1 = *(const float4*)(Z + (size_t)(t + 2) * tstr + base + 4);
        }

        float s1 = 0.f, s2 = 0.f;
        #pragma unroll
        for (int q = 0; q < 8; q++) { s1 += y[q]; s2 += y[q] * y[q]; }
        #pragma unroll
        for (int off = 16; off > 0; off >>= 1) {
            s1 += __shfl_xor_sync(0xffffffffu, s1, off);
            s2 += __shfl_xor_sync(0xffffffffu, s2, off);
        }
        float m   = s1 * (1.f / B_);
        float var = s2 * (1.f / B_) - m * m;
        float sc  = rsqrtf(var + EPS_) * gv;
        float sh  = bv - m * sc;
        #pragma unroll
        for (int q = 0; q < 8; q++) h[q] = y[q] * sc + sh;

        float* op = OUT + (size_t)t * tstr + base;
        *(float4*)(op)     = make_float4(h[0], h[1], h[2], h[3]);
        *(float4*)(op + 4) = make_float4(h[4], h[5], h[6], h[7]);
    }
}

// ---------------- head: logits + log_softmax ----------------
__global__ void __launch_bounds__(256) head_kernel(
    const float* __restrict__ HM,   // [j][i] slice (t = T-1)
    const float* __restrict__ Wfc, const float* __restrict__ bfc,
    float* __restrict__ out) {

    __shared__ float hrow[H_];
    __shared__ float shd[8];

    const int r   = blockIdx.x;
    const int tid = threadIdx.x;

    hrow[tid]       = HM[(size_t)tid * 256 + r];
    hrow[tid + 256] = HM[(size_t)(tid + 256) * 256 + r];
    __syncthreads();

    float acc = bfc[tid];
    const float4* wrow = (const float4*)(Wfc + (size_t)tid * H_);
    #pragma unroll 4
    for (int j4 = 0; j4 < H_ / 4; j4++) {
        float4 w = wrow[j4];
        acc = fmaf(hrow[4 * j4 + 0], w.x, acc);
        acc = fmaf(hrow[4 * j4 + 1], w.y, acc);
        acc = fmaf(hrow[4 * j4 + 2], w.z, acc);
        acc = fmaf(hrow[4 * j4 + 3], w.w, acc);
    }

    float v = acc;
    #pragma unroll
    for (int off = 16; off > 0; off >>= 1)
        v = fmaxf(v, __shfl_xor_sync(0xffffffffu, v, off));
    if ((tid & 31) == 0) shd[tid >> 5] = v;
    __syncthreads();
    float mx = shd[0];
    #pragma unroll
    for (int w = 1; w < 8; w++) mx = fmaxf(mx, shd[w]);
    __syncthreads();

    float e = expf(acc - mx);
    float sv = e;
    #pragma unroll
    for (int off = 16; off > 0; off >>= 1)
        sv += __shfl_xor_sync(0xffffffffu, sv, off);
    if ((tid & 31) == 0) shd[tid >> 5] = sv;
    __syncthreads();
    float se = 0.f;
    #pragma unroll
    for (int w = 0; w < 8; w++) se += shd[w];

    out[(size_t)r * O_ + tid] = acc - mx - logf(se);
}

// ---------------- harness entry ----------------
extern "C" void kernel_launch(void* const* d_in, const int* in_sizes, int n_in,
                              void* d_out, int out_size) {
    (void)in_sizes; (void)n_in; (void)out_size;
    const float* x    = (const float*)d_in[0];
    const float* W0   = (const float*)d_in[1];
    const float* b0   = (const float*)d_in[2];
    const float* u0   = (const float*)d_in[3];
    const float* g10  = (const float*)d_in[4];
    const float* be10 = (const float*)d_in[5];
    const float* g20  = (const float*)d_in[6];
    const float* be20 = (const float*)d_in[7];
    const float* Wm   = (const float*)d_in[8];
    const float* bm   = (const float*)d_in[9];
    const float* um   = (const float*)d_in[10];
    const float* g1m  = (const float*)d_in[11];
    const float* be1m = (const float*)d_in[12];
    const float* g2m  = (const float*)d_in[13];
    const float* be2m = (const float*)d_in[14];
    const float* Wfc  = (const float*)d_in[15];
    const float* bfc  = (const float*)d_in[16];
    float* out = (float*)d_out;

    static int attr_set = 0;
    if (!attr_set) {
        cudaFuncSetAttribute(gemm_bn_kernel,
                             cudaFuncAttributeMaxDynamicSharedMemorySize, GEMM_SMEM);
        attr_set = 1;
    }

    float* bufA;  cudaGetSymbolAddress((void**)&bufA, d_bufA);
    float* bufB;  cudaGetSymbolAddress((void**)&bufB, d_bufB);
    float* xT;    cudaGetSymbolAddress((void**)&xT,   d_xT);

    // x -> xT
    transpose_kernel<<<dim3(T_, D_ / 32, B_ / 32), dim3(32, 32)>>>(x);
    // layer 0
    gemm_bn_kernel<<<dim3(T_, H_ / TJ_), GT_, GEMM_SMEM>>>(xT, W0, b0, g10, be10, bufA);
    scan_kernel<<<128, 128>>>(bufA, u0, g20, be20, bufB);
    // middle layer 1
    gemm_bn_kernel<<<dim3(T_, H_ / TJ_), GT_, GEMM_SMEM>>>(bufB, Wm, bm, g1m, be1m, bufA);
    scan_kernel<<<128, 128>>>(bufA, um, g2m, be2m, bufB);
    // middle layer 2
    gemm_bn_kernel<<<dim3(T_, H_ / TJ_), GT_, GEMM_SMEM>>>(bufB, Wm, bm, g1m, be1m, bufA);
    scan_kernel<<<128, 128>>>(bufA, um, g2m, be2m, bufB);
    // head on final hm1 slice
    head_kernel<<<O_, 256>>>(bufB + (size_t)(T_ - 1) * H_ * B_, Wfc, bfc, out);
}